// round 17
// baseline (speedup 1.0000x reference)
#include <cuda_runtime.h>
#include <cstdint>
#include <cstddef>

#define N_NODES 10000
#define N_EDGES 160000
typedef unsigned long long ull;

// ---------------- scratch ----------------
__device__ float g_Y [N_NODES * 256];
__device__ float g_R [N_NODES * 256];
__device__ float g_H [N_NODES * 256];
__device__ float4 g_F [N_NODES];
__device__ int   g_cnt[N_NODES];          // zero-initialized by loader; re-zeroed in scan
__device__ int   g_off[N_NODES + 1];
__device__ int   g_cur[N_NODES];
__device__ int   g_csr[N_EDGES];

// ---------------- big fused GEMM (64x128, plain-B + reg dup, 4 blocks/SM) ----------------
__global__ __launch_bounds__(256, 4)
void sage_gemm4_kernel(const float* __restrict__ X,
                       const float* __restrict__ Wl, const float* __restrict__ Wr)
{
    constexpr int BK = 16, ASTRIDE = 72;
    __shared__ float AsT[BK][ASTRIDE];
    __shared__ __align__(16) float Bs[BK][128];

    int tid = threadIdx.x;
    int bx = blockIdx.x;
    int lane = tid & 31, wid = tid >> 5;
    int bm0 = blockIdx.y * 64;
    const float* B = (bx < 2) ? Wl : Wr;
    float* C = (bx < 2) ? g_Y : g_R;
    int bn0 = (bx & 1) * 128;

    int rA = tid >> 2, qA = tid & 3;
    int rB = tid >> 5, cB = tid & 31;
    int rowA = bm0 + rA;
    const float* pA = X + (size_t)rowA * 512 + qA * 4;
    const float* pB0 = B + (size_t)rB * 256 + bn0 + cB * 4;
    const float* pB1 = B + (size_t)(rB + 8) * 256 + bn0 + cB * 4;

    ull acc2[4][4];
#pragma unroll
    for (int i = 0; i < 4; i++)
#pragma unroll
        for (int j = 0; j < 4; j++) acc2[i][j] = 0ull;

    for (int c = 0; c < 32; c++) {
        int k0 = c * BK;
        float4 a = (rowA < N_NODES) ? *(const float4*)(pA + k0)
                                    : make_float4(0.f, 0.f, 0.f, 0.f);
        float4 b0 = *(const float4*)(pB0 + (size_t)k0 * 256);
        float4 b1 = *(const float4*)(pB1 + (size_t)k0 * 256);

        AsT[qA * 4 + 0][rA] = a.x;
        AsT[qA * 4 + 1][rA] = a.y;
        AsT[qA * 4 + 2][rA] = a.z;
        AsT[qA * 4 + 3][rA] = a.w;
        *(float4*)&Bs[rB][cB * 4]     = b0;
        *(float4*)&Bs[rB + 8][cB * 4] = b1;
        __syncthreads();

#pragma unroll
        for (int k = 0; k < BK; k++) {
            const ulonglong2* ap = (const ulonglong2*)&AsT[k][wid * 8];
            ulonglong2 a01 = ap[0], a23 = ap[1];
            ull av[4] = { a01.x, a01.y, a23.x, a23.y };
            float2 f0 = *(const float2*)&Bs[k][2 * lane];
            float2 f1 = *(const float2*)&Bs[k][2 * lane + 64];
            ull b00, b01, b10, b11;
            asm("mov.b64 %0, {%1, %1};" : "=l"(b00) : "f"(f0.x));
            asm("mov.b64 %0, {%1, %1};" : "=l"(b01) : "f"(f0.y));
            asm("mov.b64 %0, {%1, %1};" : "=l"(b10) : "f"(f1.x));
            asm("mov.b64 %0, {%1, %1};" : "=l"(b11) : "f"(f1.y));
#pragma unroll
            for (int i = 0; i < 4; i++) {
                asm("fma.rn.f32x2 %0, %1, %2, %0;" : "+l"(acc2[i][0]) : "l"(av[i]), "l"(b00));
                asm("fma.rn.f32x2 %0, %1, %2, %0;" : "+l"(acc2[i][1]) : "l"(av[i]), "l"(b01));
                asm("fma.rn.f32x2 %0, %1, %2, %0;" : "+l"(acc2[i][2]) : "l"(av[i]), "l"(b10));
                asm("fma.rn.f32x2 %0, %1, %2, %0;" : "+l"(acc2[i][3]) : "l"(av[i]), "l"(b11));
            }
        }
        __syncthreads();
    }

#pragma unroll
    for (int i = 0; i < 4; i++) {
#pragma unroll
        for (int p = 0; p < 2; p++) {
            int row = bm0 + wid * 8 + 2 * i + p;
            if (row >= N_NODES) continue;
#pragma unroll
            for (int jj = 0; jj < 2; jj++) {
                int col = bn0 + 2 * lane + 64 * jj;
                ull u0 = acc2[i][2 * jj], u1 = acc2[i][2 * jj + 1];
                float v0 = __uint_as_float(p ? (unsigned)(u0 >> 32) : (unsigned)u0);
                float v1 = __uint_as_float(p ? (unsigned)(u1 >> 32) : (unsigned)u1);
                *(float2*)(C + (size_t)row * 256 + col) = make_float2(v0, v1);
            }
        }
    }
}

// ---------------- CSR chain (side stream) ----------------
__global__ void count_kernel(const int* __restrict__ ei) {
    int e = blockIdx.x * blockDim.x + threadIdx.x;
    if (e < N_EDGES) atomicAdd(&g_cnt[ei[N_EDGES + e]], 1);
}

__global__ void scan_kernel() {
    __shared__ int stage[10240];
    __shared__ int wsum[32];
    int t = threadIdx.x;
    int lane = t & 31, w = t >> 5;
#pragma unroll
    for (int i = 0; i < 10; i++) {
        int idx = t + i * 1024;
        stage[idx] = (idx < N_NODES) ? g_cnt[idx] : 0;
    }
    __syncthreads();
    int base = t * 10;
    int local[10];
    int s = 0;
#pragma unroll
    for (int i = 0; i < 10; i++) { local[i] = stage[base + i]; s += local[i]; }
    int v = s;
#pragma unroll
    for (int o = 1; o < 32; o <<= 1) {
        int u = __shfl_up_sync(0xFFFFFFFFu, v, o);
        if (lane >= o) v += u;
    }
    if (lane == 31) wsum[w] = v;
    __syncthreads();
    if (w == 0) {
        int x2 = wsum[lane];
#pragma unroll
        for (int o = 1; o < 32; o <<= 1) {
            int u = __shfl_up_sync(0xFFFFFFFFu, x2, o);
            if (lane >= o) x2 += u;
        }
        wsum[lane] = x2;
    }
    __syncthreads();
    int pre = v - s + (w > 0 ? wsum[w - 1] : 0);
#pragma unroll
    for (int i = 0; i < 10; i++) { stage[base + i] = pre; pre += local[i]; }
    if (t == 1023) g_off[N_NODES] = wsum[31];
    __syncthreads();
#pragma unroll
    for (int i = 0; i < 10; i++) {
        int idx = t + i * 1024;
        if (idx < N_NODES) {
            int p = stage[idx];
            g_off[idx] = p;
            g_cur[idx] = p;
            g_cnt[idx] = 0;
        }
    }
}

__global__ void scatter_kernel(const int* __restrict__ ei) {
    int e = blockIdx.x * blockDim.x + threadIdx.x;
    if (e < N_EDGES) {
        int s = ei[e];
        int d = ei[N_EDGES + e];
        int p = atomicAdd(&g_cur[d], 1);
        g_csr[p] = s;
    }
}

// ---------------- aggregation: 2 warps per node, 4-edge unroll ----------------
__global__ void aggr_kernel(const float* __restrict__ b_l) {
    int gw = (blockIdx.x * blockDim.x + threadIdx.x) >> 5;
    int node = gw >> 1;
    int half = gw & 1;
    int lane = threadIdx.x & 31;
    if (node >= N_NODES) return;
    int s0 = g_off[node], s1 = g_off[node + 1];

    int fi = half * 32 + lane;
    float4 a = make_float4(0.f, 0.f, 0.f, 0.f);
    const float4* Y4 = (const float4*)g_Y;
    int e = s0;
    for (; e + 3 < s1; e += 4) {
        int sa = g_csr[e], sb = g_csr[e + 1], sc = g_csr[e + 2], sd = g_csr[e + 3];
        float4 va = __ldg(&Y4[(size_t)sa * 64 + fi]);
        float4 vb = __ldg(&Y4[(size_t)sb * 64 + fi]);
        float4 vc = __ldg(&Y4[(size_t)sc * 64 + fi]);
        float4 vd = __ldg(&Y4[(size_t)sd * 64 + fi]);
        a.x += va.x; a.y += va.y; a.z += va.z; a.w += va.w;
        a.x += vb.x; a.y += vb.y; a.z += vb.z; a.w += vb.w;
        a.x += vc.x; a.y += vc.y; a.z += vc.z; a.w += vc.w;
        a.x += vd.x; a.y += vd.y; a.z += vd.z; a.w += vd.w;
    }
    for (; e < s1; e++) {
        int sa = g_csr[e];
        float4 v = __ldg(&Y4[(size_t)sa * 64 + fi]);
        a.x += v.x; a.y += v.y; a.z += v.z; a.w += v.w;
    }
    int deg = s1 - s0;
    float inv = (deg > 0) ? 1.0f / (float)deg : 1.0f;

    const float4* R4 = (const float4*)g_R;
    const float4* BL = (const float4*)b_l;
    float4* H4 = (float4*)g_H;

    float4 r = R4[(size_t)node * 64 + fi];
    float4 bl = BL[fi];
    float4 o;
    o.x = fmaxf(a.x * inv + bl.x + r.x, 0.f);
    o.y = fmaxf(a.y * inv + bl.y + r.y, 0.f);
    o.z = fmaxf(a.z * inv + bl.z + r.z, 0.f);
    o.w = fmaxf(a.w * inv + bl.w + r.w, 0.f);
    H4[(size_t)node * 64 + fi] = o;
}

// ---------------- fused MLP (256->128->64->32->3) + features ----------------
#define S2 66
#define SA 68
#define MLP_SMEM ((128 * S2 + 64 * S2 + 32 * S2 + 2048 + 16 * SA) * 4)

__global__ __launch_bounds__(256)
void mlp_kernel(const float* __restrict__ Wa, const float* __restrict__ ba,
                const float* __restrict__ W1, const float* __restrict__ b1,
                const float* __restrict__ W2, const float* __restrict__ b2,
                const float* __restrict__ W3, const float* __restrict__ b3)
{
    extern __shared__ __align__(16) float sm[];
    float* H2s = sm;
    float* H3s = H2s + 128 * S2;
    float* H4s = H3s + 64 * S2;
    float* Ws  = H4s + 32 * S2;
    float* Ast = Ws + 2048;

    int tid = threadIdx.x;
    int tx = tid & 15, ty = tid >> 4;
    int bm0 = blockIdx.x * 64;

    {   // layer 1
        ull acc[2][8];
#pragma unroll
        for (int i = 0; i < 2; i++)
#pragma unroll
            for (int j = 0; j < 8; j++) acc[i][j] = 0ull;

        int r = tid >> 2, q = tid & 3;
        int row = bm0 + r;
        for (int k0 = 0; k0 < 256; k0 += 16) {
            float4 v = make_float4(0.f, 0.f, 0.f, 0.f);
            if (row < N_NODES) v = *(const float4*)(g_H + (size_t)row * 256 + k0 + q * 4);
            Ast[(q * 4 + 0) * SA + r] = v.x;
            Ast[(q * 4 + 1) * SA + r] = v.y;
            Ast[(q * 4 + 2) * SA + r] = v.z;
            Ast[(q * 4 + 3) * SA + r] = v.w;
#pragma unroll
            for (int idx = tid; idx < 2048; idx += 256) {
                int rr = idx >> 7, cc = idx & 127;
                Ws[idx] = Wa[(size_t)(k0 + rr) * 128 + cc];
            }
            __syncthreads();
#pragma unroll
            for (int k = 0; k < 16; k++) {
                ull av0 = *(const ull*)&Ast[k * SA + ty * 4];
                ull av1 = *(const ull*)&Ast[k * SA + ty * 4 + 2];
#pragma unroll
                for (int j = 0; j < 4; j++) {
                    float2 f = *(const float2*)&Ws[k * 128 + 2 * tx + 32 * j];
                    ull bp0, bp1;
                    asm("mov.b64 %0, {%1, %1};" : "=l"(bp0) : "f"(f.x));
                    asm("mov.b64 %0, {%1, %1};" : "=l"(bp1) : "f"(f.y));
                    asm("fma.rn.f32x2 %0, %1, %2, %0;" : "+l"(acc[0][2 * j])     : "l"(av0), "l"(bp0));
                    asm("fma.rn.f32x2 %0, %1, %2, %0;" : "+l"(acc[1][2 * j])     : "l"(av1), "l"(bp0));
                    asm("fma.rn.f32x2 %0, %1, %2, %0;" : "+l"(acc[0][2 * j + 1]) : "l"(av0), "l"(bp1));
                    asm("fma.rn.f32x2 %0, %1, %2, %0;" : "+l"(acc[1][2 * j + 1]) : "l"(av1), "l"(bp1));
                }
            }
            __syncthreads();
        }
#pragma unroll
        for (int i = 0; i < 2; i++)
#pragma unroll
            for (int p = 0; p < 2; p++) {
                int rl = ty * 4 + 2 * i + p;
#pragma unroll
                for (int j = 0; j < 4; j++) {
                    int col = 2 * tx + 32 * j;
                    ull u0 = acc[i][2 * j], u1 = acc[i][2 * j + 1];
                    float v0 = __uint_as_float(p ? (unsigned)(u0 >> 32) : (unsigned)u0) + ba[col];
                    float v1 = __uint_as_float(p ? (unsigned)(u1 >> 32) : (unsigned)u1) + ba[col + 1];
                    H2s[col * S2 + rl]       = fmaxf(v0, 0.f);
                    H2s[(col + 1) * S2 + rl] = fmaxf(v1, 0.f);
                }
            }
        __syncthreads();
    }

    {   // layer 2
        ull acc[2][4];
#pragma unroll
        for (int i = 0; i < 2; i++)
#pragma unroll
            for (int j = 0; j < 4; j++) acc[i][j] = 0ull;

        for (int k0 = 0; k0 < 128; k0 += 16) {
#pragma unroll
            for (int idx = tid; idx < 1024; idx += 256) {
                int rr = idx >> 6, cc = idx & 63;
                Ws[idx] = W1[(size_t)(k0 + rr) * 64 + cc];
            }
            __syncthreads();
#pragma unroll
            for (int k = 0; k < 16; k++) {
                ull av0 = *(const ull*)&H2s[(k0 + k) * S2 + ty * 4];
                ull av1 = *(const ull*)&H2s[(k0 + k) * S2 + ty * 4 + 2];
#pragma unroll
                for (int j = 0; j < 2; j++) {
                    float2 f = *(const float2*)&Ws[k * 64 + 2 * tx + 32 * j];
                    ull bp0, bp1;
                    asm("mov.b64 %0, {%1, %1};" : "=l"(bp0) : "f"(f.x));
                    asm("mov.b64 %0, {%1, %1};" : "=l"(bp1) : "f"(f.y));
                    asm("fma.rn.f32x2 %0, %1, %2, %0;" : "+l"(acc[0][2 * j])     : "l"(av0), "l"(bp0));
                    asm("fma.rn.f32x2 %0, %1, %2, %0;" : "+l"(acc[1][2 * j])     : "l"(av1), "l"(bp0));
                    asm("fma.rn.f32x2 %0, %1, %2, %0;" : "+l"(acc[0][2 * j + 1]) : "l"(av0), "l"(bp1));
                    asm("fma.rn.f32x2 %0, %1, %2, %0;" : "+l"(acc[1][2 * j + 1]) : "l"(av1), "l"(bp1));
                }
            }
            __syncthreads();
        }
#pragma unroll
        for (int i = 0; i < 2; i++)
#pragma unroll
            for (int p = 0; p < 2; p++) {
                int rl = ty * 4 + 2 * i + p;
#pragma unroll
                for (int j = 0; j < 2; j++) {
                    int col = 2 * tx + 32 * j;
                    ull u0 = acc[i][2 * j], u1 = acc[i][2 * j + 1];
                    float v0 = __uint_as_float(p ? (unsigned)(u0 >> 32) : (unsigned)u0) + b1[col];
                    float v1 = __uint_as_float(p ? (unsigned)(u1 >> 32) : (unsigned)u1) + b1[col + 1];
                    H3s[col * S2 + rl]       = fmaxf(v0, 0.f);
                    H3s[(col + 1) * S2 + rl] = fmaxf(v1, 0.f);
                }
            }
        __syncthreads();
    }

    {   // layer 3
        ull acc[2][2];
#pragma unroll
        for (int i = 0; i < 2; i++)
#pragma unroll
            for (int j = 0; j < 2; j++) acc[i][j] = 0ull;

        for (int k0 = 0; k0 < 64; k0 += 16) {
#pragma unroll
            for (int idx = tid; idx < 512; idx += 256) {
                int rr = idx >> 5, cc = idx & 31;
                Ws[idx] = W2[(size_t)(k0 + rr) * 32 + cc];
            }
            __syncthreads();
#pragma unroll
            for (int k = 0; k < 16; k++) {
                ull av0 = *(const ull*)&H3s[(k0 + k) * S2 + ty * 4];
                ull av1 = *(const ull*)&H3s[(k0 + k) * S2 + ty * 4 + 2];
                float2 f = *(const float2*)&Ws[k * 32 + 2 * tx];
                ull bp0, bp1;
                asm("mov.b64 %0, {%1, %1};" : "=l"(bp0) : "f"(f.x));
                asm("mov.b64 %0, {%1, %1};" : "=l"(bp1) : "f"(f.y));
                asm("fma.rn.f32x2 %0, %1, %2, %0;" : "+l"(acc[0][0]) : "l"(av0), "l"(bp0));
                asm("fma.rn.f32x2 %0, %1, %2, %0;" : "+l"(acc[1][0]) : "l"(av1), "l"(bp0));
                asm("fma.rn.f32x2 %0, %1, %2, %0;" : "+l"(acc[0][1]) : "l"(av0), "l"(bp1));
                asm("fma.rn.f32x2 %0, %1, %2, %0;" : "+l"(acc[1][1]) : "l"(av1), "l"(bp1));
            }
            __syncthreads();
        }
#pragma unroll
        for (int i = 0; i < 2; i++)
#pragma unroll
            for (int p = 0; p < 2; p++) {
                int rl = ty * 4 + 2 * i + p;
                int col = 2 * tx;
                ull u0 = acc[i][0], u1 = acc[i][1];
                float v0 = __uint_as_float(p ? (unsigned)(u0 >> 32) : (unsigned)u0) + b2[col];
                float v1 = __uint_as_float(p ? (unsigned)(u1 >> 32) : (unsigned)u1) + b2[col + 1];
                H4s[col * S2 + rl]       = fmaxf(v0, 0.f);
                H4s[(col + 1) * S2 + rl] = fmaxf(v1, 0.f);
            }
        __syncthreads();
    }

    if (tid < 64) {
        int grow = bm0 + tid;
        if (grow < N_NODES) {
            float a0 = b3[0], a1 = b3[1], a2 = b3[2];
#pragma unroll
            for (int k = 0; k < 32; k++) {
                float hv = H4s[k * S2 + tid];
                a0 += hv * W3[k * 3 + 0];
                a1 += hv * W3[k * 3 + 1];
                a2 += hv * W3[k * 3 + 2];
            }
            g_F[grow] = make_float4(a0, a1, a2, a0 * a0 + a1 * a1 + a2 * a2);
        }
    }
}

// ---------------- pairwise L2 (streaming stores) ----------------
__device__ __forceinline__ float pdist(float4 a, float4 b) {
    float d2 = a.w + b.w - 2.0f * (a.x * b.x + a.y * b.y + a.z * b.z);
    if (d2 <= 0.f) return 0.f;
    float r;
    asm("sqrt.approx.f32 %0, %1;" : "=f"(r) : "f"(d2));
    return r;
}

__global__ __launch_bounds__(256)
void dist_kernel(float* __restrict__ out) {
    __shared__ float4 si[128], sj[128];
    int bi = blockIdx.y * 128, bj = blockIdx.x * 128;
    int t = threadIdx.x;
    if (t < 128) {
        int i = bi + t;
        si[t] = (i < N_NODES) ? g_F[i] : make_float4(0.f, 0.f, 0.f, 0.f);
    } else {
        int j = bj + t - 128;
        sj[t - 128] = (j < N_NODES) ? g_F[j] : make_float4(0.f, 0.f, 0.f, 0.f);
    }
    __syncthreads();

    int c4 = t & 31;
    int rb = t >> 5;
    int j0 = bj + c4 * 4;
    if (j0 >= N_NODES) return;

    float4 b0 = sj[c4 * 4 + 0];
    float4 b1 = sj[c4 * 4 + 1];
    float4 b2 = sj[c4 * 4 + 2];
    float4 b3 = sj[c4 * 4 + 3];

#pragma unroll 4
    for (int rr = 0; rr < 16; rr++) {
        int r = rb * 16 + rr;
        int i = bi + r;
        if (i >= N_NODES) break;
        float4 a = si[r];
        float4 o;
        o.x = pdist(a, b0);
        o.y = pdist(a, b1);
        o.z = pdist(a, b2);
        o.w = pdist(a, b3);
        float* p = out + (size_t)i * N_NODES + j0;
        asm volatile("st.global.cs.v4.f32 [%0], {%1,%2,%3,%4};"
                     :: "l"(p), "f"(o.x), "f"(o.y), "f"(o.z), "f"(o.w) : "memory");
    }
}

// ---------------- launch ----------------
extern "C" void kernel_launch(void* const* d_in, const int* in_sizes, int n_in,
                              void* d_out, int out_size)
{
    const float* x   = (const float*)d_in[0];
    const int*   ei  = (const int*)d_in[1];
    const float* W_l = (const float*)d_in[2];
    const float* b_l = (const float*)d_in[3];
    const float* W_r = (const float*)d_in[4];
    const float* Wa  = (const float*)d_in[5];
    const float* ba  = (const float*)d_in[6];
    const float* W1  = (const float*)d_in[7];
    const float* b1  = (const float*)d_in[8];
    const float* W2  = (const float*)d_in[9];
    const float* b2  = (const float*)d_in[10];
    const float* W3  = (const float*)d_in[11];
    const float* b3  = (const float*)d_in[12];
    float* out = (float*)d_out;

    static cudaStream_t s2;
    static cudaEvent_t ev0, ev1;
    static int init_done = 0;
    if (!init_done) {
        cudaStreamCreateWithFlags(&s2, cudaStreamNonBlocking);
        cudaEventCreateWithFlags(&ev0, cudaEventDisableTiming);
        cudaEventCreateWithFlags(&ev1, cudaEventDisableTiming);
        cudaFuncSetAttribute(mlp_kernel,
                             cudaFuncAttributeMaxDynamicSharedMemorySize, MLP_SMEM);
        init_done = 1;
    }

    const int MBLK = (N_NODES + 127) / 128;   // 79
    const int MBLK64 = (N_NODES + 63) / 64;   // 157

    // fork: CSR chain on side stream, GEMM on main stream
    cudaEventRecord(ev0, 0);
    cudaStreamWaitEvent(s2, ev0, 0);
    count_kernel<<<(N_EDGES + 255) / 256, 256, 0, s2>>>(ei);
    scan_kernel<<<1, 1024, 0, s2>>>();
    scatter_kernel<<<(N_EDGES + 255) / 256, 256, 0, s2>>>(ei);
    cudaEventRecord(ev1, s2);

    sage_gemm4_kernel<<<dim3(4, MBLK64), 256>>>(x, W_l, W_r);

    // join, then rest of the pipeline
    cudaStreamWaitEvent(0, ev1, 0);
    aggr_kernel<<<(N_NODES * 2 * 32 + 255) / 256, 256>>>(b_l);
    mlp_kernel<<<MBLK64, 256, MLP_SMEM>>>(Wa, ba, W1, b1, W2, b2, W3, b3);
    dist_kernel<<<dim3(MBLK, MBLK), 256>>>(out);

    (void)in_sizes; (void)n_in; (void)out_size;
}